// round 16
// baseline (speedup 1.0000x reference)
#include <cuda_runtime.h>

#define NN 100000
#define EE 1600000
#define CC 16
#define HH 32
#define NLAY 8
#define TPB 256
#define PTPB 128
#define MTPB 64
#define MBLK 6
#define MGRID (148 * MBLK) // 6 blocks/SM x 148 SMs, co-resident via __launch_bounds__(64,6)
#define NCHUNK 12500       // (EE/2)/64
#define MAXIT 10
#define THRESH 5000        // count <= 5000  <=>  ratio <= 0.05 (exact in fp32)

// ---------------- device scratch ----------------
__device__ unsigned int        g_mkey[NN];
__device__ double              g_ssum[NN];
__device__ float2              g_ms[NN];       // (max_logit_f32, (float)ssum) per node
__device__ float               g_tmp[EE];
__device__ float               g_score[EE];
__device__ unsigned long long  g_packs[NN];
__device__ unsigned long long  g_packd[NN];
__device__ int                 g_maxidx[NN];
__device__ int                 g_part[NN];
__device__ unsigned char       g_nrem[NN];
__device__ unsigned char       g_rm[NN];
__device__ unsigned char       g_live[NN];     // nrem && !rm (written by k_B)
__device__ int                 g_cnt[MAXIT];
__device__ int                 g_lc[2];
__device__ int4                g_list[2][EE];
__device__ float               g_P[NN * HH];   // x @ W0[:16] + b0  (src half)
__device__ float               g_Q[NN * HH];   // x @ W0[16:]       (dst half)
__device__ int                 g_stat[NN];     // livebit | (part+1)<<1

__device__ __forceinline__ unsigned int fkey(float f) {
    unsigned int b = __float_as_uint(f);
    return (b & 0x80000000u) ? ~b : (b | 0x80000000u);
}
__device__ __forceinline__ float fkey_inv(unsigned int k) {
    unsigned int b = (k & 0x80000000u) ? (k ^ 0x80000000u) : ~k;
    return __uint_as_float(b);
}
__device__ __forceinline__ bool iter_done(int t) {
    return (t > 0) && (g_cnt[t - 1] <= THRESH);
}
__device__ __forceinline__ unsigned long long mkpk(float sc, int eid) {
    return ((unsigned long long)__float_as_uint(sc) << 32) | (unsigned int)(EE - eid);
}

// ---------------- layer-1 per-node precompute + global init (fused) ----------------
__global__ void __launch_bounds__(PTPB)
k_pre(const float* __restrict__ x, const float* __restrict__ Wh,
      const float* __restrict__ bh) {
    __shared__ __align__(16) float W0[HH * HH];
    __shared__ float b0[HH];
    for (int i = threadIdx.x; i < HH * HH; i += blockDim.x) W0[i] = Wh[i];
    if (threadIdx.x < HH) b0[threadIdx.x] = bh[threadIdx.x];
    __syncthreads();

    int n = blockIdx.x * blockDim.x + threadIdx.x;

    if (n < NN) {
        g_mkey[n] = 0u;
        g_ssum[n] = 0.0;
        g_packs[n] = 0ull;       // score=0.0f, eid=E (matches empty-segment fill)
        g_packd[n] = 0ull;
        g_nrem[n] = 1;
        g_rm[n] = 0;
        g_part[n] = -1;
    }
    if (n < MAXIT) g_cnt[n] = 0;
    if (n < 2) g_lc[n] = 0;

    if (n >= NN) return;

    float xv[CC];
    const float4* xp = (const float4*)(x + (size_t)n * CC);
#pragma unroll
    for (int q = 0; q < 4; q++) {
        float4 v = xp[q];
        xv[4 * q] = v.x; xv[4 * q + 1] = v.y; xv[4 * q + 2] = v.z; xv[4 * q + 3] = v.w;
    }
    float a[HH];
#pragma unroll
    for (int j = 0; j < HH; j++) a[j] = b0[j];
#pragma unroll
    for (int k = 0; k < CC; k++) {
        float xk = xv[k];
        const float4* w4 = (const float4*)(W0 + k * HH);
#pragma unroll
        for (int j = 0; j < HH / 4; j++) {
            float4 w = w4[j];
            a[4 * j] = fmaf(xk, w.x, a[4 * j]);
            a[4 * j + 1] = fmaf(xk, w.y, a[4 * j + 1]);
            a[4 * j + 2] = fmaf(xk, w.z, a[4 * j + 2]);
            a[4 * j + 3] = fmaf(xk, w.w, a[4 * j + 3]);
        }
    }
    float4* Pp = (float4*)(g_P + (size_t)n * HH);
#pragma unroll
    for (int j = 0; j < HH / 4; j++)
        Pp[j] = make_float4(a[4 * j], a[4 * j + 1], a[4 * j + 2], a[4 * j + 3]);

#pragma unroll
    for (int j = 0; j < HH; j++) a[j] = 0.0f;
#pragma unroll
    for (int k = 0; k < CC; k++) {
        float xk = xv[k];
        const float4* w4 = (const float4*)(W0 + (CC + k) * HH);
#pragma unroll
        for (int j = 0; j < HH / 4; j++) {
            float4 w = w4[j];
            a[4 * j] = fmaf(xk, w.x, a[4 * j]);
            a[4 * j + 1] = fmaf(xk, w.y, a[4 * j + 1]);
            a[4 * j + 2] = fmaf(xk, w.z, a[4 * j + 2]);
            a[4 * j + 3] = fmaf(xk, w.w, a[4 * j + 3]);
        }
    }
    float4* Qp = (float4*)(g_Q + (size_t)n * HH);
#pragma unroll
    for (int j = 0; j < HH / 4; j++)
        Qp[j] = make_float4(a[4 * j], a[4 * j + 1], a[4 * j + 2], a[4 * j + 3]);
}

// ---------------- edge MLP layers 2..8, grid-stride persistent, 2 edges/thread -------
// Per-edge arithmetic is bit-identical to rounds 6..15 (same FMA order).
__global__ void __launch_bounds__(MTPB, MBLK)
k_mlp(const int* __restrict__ ei,
      const float* __restrict__ Wh, const float* __restrict__ bh,
      const float* __restrict__ Wo, const float* __restrict__ bo) {
    __shared__ __align__(16) float Wsh[(NLAY - 1) * HH * HH];
    __shared__ float bsh[(NLAY - 1) * HH];
    __shared__ float Wosh[HH];
    __shared__ float bosh;
    {
        const float4* src = (const float4*)(Wh + HH * HH);
        float4* dst = (float4*)Wsh;
        for (int i = threadIdx.x; i < (NLAY - 1) * HH * HH / 4; i += MTPB)
            dst[i] = src[i];
    }
    for (int i = threadIdx.x; i < (NLAY - 1) * HH; i += MTPB)
        bsh[i] = bh[HH + i];
    if (threadIdx.x < HH) Wosh[threadIdx.x] = Wo[threadIdx.x];
    if (threadIdx.x == 0) bosh = bo[0];
    __syncthreads();

    int c = blockIdx.x;
    if (c >= NCHUNK) return;
    int i0 = c * MTPB + threadIdx.x;
    int sA = ei[i0], dA = ei[EE + i0];
    int sB = ei[i0 + EE / 2], dB = ei[EE + i0 + EE / 2];

#pragma unroll 1
    for (; c < NCHUNK; c += MGRID) {
        int i = c * MTPB + threadIdx.x;   // 0 .. EE/2-1
        int eA = i;
        int eB = i + (EE / 2);

        // prefetch next chunk's indices (independent loads, scheduled early)
        int nsA = 0, ndA = 0, nsB = 0, ndB = 0;
        int cn = c + MGRID;
        if (cn < NCHUNK) {
            int in = cn * MTPB + threadIdx.x;
            nsA = ei[in];
            ndA = ei[EE + in];
            nsB = ei[in + EE / 2];
            ndB = ei[EE + in + EE / 2];
        }

        float h[2][HH];
        {
            const float4* PA = (const float4*)(g_P + (size_t)sA * HH);
            const float4* QA = (const float4*)(g_Q + (size_t)dA * HH);
            const float4* PB = (const float4*)(g_P + (size_t)sB * HH);
            const float4* QB = (const float4*)(g_Q + (size_t)dB * HH);
#pragma unroll
            for (int q = 0; q < HH / 4; q++) {
                float4 pa = PA[q], qa = QA[q];
                float4 pb = PB[q], qb = QB[q];
                h[0][4 * q + 0] = fmaxf(pa.x + qa.x, 0.0f);
                h[0][4 * q + 1] = fmaxf(pa.y + qa.y, 0.0f);
                h[0][4 * q + 2] = fmaxf(pa.z + qa.z, 0.0f);
                h[0][4 * q + 3] = fmaxf(pa.w + qa.w, 0.0f);
                h[1][4 * q + 0] = fmaxf(pb.x + qb.x, 0.0f);
                h[1][4 * q + 1] = fmaxf(pb.y + qb.y, 0.0f);
                h[1][4 * q + 2] = fmaxf(pb.z + qb.z, 0.0f);
                h[1][4 * q + 3] = fmaxf(pb.w + qb.w, 0.0f);
            }
        }

#pragma unroll 1
        for (int l = 0; l < NLAY - 1; l++) {
            float o[2][HH];
#pragma unroll
            for (int j = 0; j < HH; j++) {
                float bb = bsh[l * HH + j];
                o[0][j] = bb;
                o[1][j] = bb;
            }
            const float* Wl = Wsh + l * HH * HH;
#pragma unroll
            for (int k = 0; k < HH; k++) {
                float hA = h[0][k], hB = h[1][k];
                const float4* w4 = (const float4*)(Wl + k * HH);
#pragma unroll
                for (int j = 0; j < HH / 4; j++) {
                    float4 w = w4[j];
                    o[0][4 * j + 0] = fmaf(hA, w.x, o[0][4 * j + 0]);
                    o[0][4 * j + 1] = fmaf(hA, w.y, o[0][4 * j + 1]);
                    o[0][4 * j + 2] = fmaf(hA, w.z, o[0][4 * j + 2]);
                    o[0][4 * j + 3] = fmaf(hA, w.w, o[0][4 * j + 3]);
                    o[1][4 * j + 0] = fmaf(hB, w.x, o[1][4 * j + 0]);
                    o[1][4 * j + 1] = fmaf(hB, w.y, o[1][4 * j + 1]);
                    o[1][4 * j + 2] = fmaf(hB, w.z, o[1][4 * j + 2]);
                    o[1][4 * j + 3] = fmaf(hB, w.w, o[1][4 * j + 3]);
                }
            }
#pragma unroll
            for (int j = 0; j < HH; j++) {
                h[0][j] = fmaxf(o[0][j], 0.0f);
                h[1][j] = fmaxf(o[1][j], 0.0f);
            }
        }

        float accA = bosh, accB = bosh;
#pragma unroll
        for (int k = 0; k < HH; k++) {
            float w = Wosh[k];
            accA = fmaf(h[0][k], w, accA);
            accB = fmaf(h[1][k], w, accB);
        }

        g_tmp[eA] = accA;
        atomicMax(&g_mkey[dA], fkey(accA));
        g_tmp[eB] = accB;
        atomicMax(&g_mkey[dB], fkey(accB));

        sA = nsA; dA = ndA; sB = nsB; dB = ndB;
    }
}

// ---------------- exp + segment sum (4 edges/thread) ----------------
__global__ void k_exp(const int* __restrict__ ei) {
    int p = blockIdx.x * blockDim.x + threadIdx.x;
    if (p >= EE / 4) return;
    int4 d4 = *(const int4*)(ei + EE + 4 * p);
    float4 t4 = *(const float4*)(g_tmp + 4 * p);
    float m0 = fkey_inv(g_mkey[d4.x]);
    float m1 = fkey_inv(g_mkey[d4.y]);
    float m2 = fkey_inv(g_mkey[d4.z]);
    float m3 = fkey_inv(g_mkey[d4.w]);
    atomicAdd(&g_ssum[d4.x], (double)expf(t4.x - m0));
    atomicAdd(&g_ssum[d4.y], (double)expf(t4.y - m1));
    atomicAdd(&g_ssum[d4.z], (double)expf(t4.z - m2));
    atomicAdd(&g_ssum[d4.w], (double)expf(t4.w - m3));
}

// ---------------- per-node (max, sum_f32) pack ----------------
__global__ void k_ms() {
    int n = blockIdx.x * blockDim.x + threadIdx.x;
    if (n >= NN) return;
    g_ms[n] = make_float2(fkey_inv(g_mkey[n]), (float)g_ssum[n]);
}

// ---------------- softmax finalize (4 edges/thread, one random 8B load/edge) --------
__global__ void k_soft(const int* __restrict__ ei) {
    int p = blockIdx.x * blockDim.x + threadIdx.x;
    if (p >= EE / 4) return;
    int4 s4 = *(const int4*)(ei + 4 * p);
    int4 d4 = *(const int4*)(ei + EE + 4 * p);
    float4 t4 = *(const float4*)(g_tmp + 4 * p);
    float2 ms0 = g_ms[d4.x];
    float2 ms1 = g_ms[d4.y];
    float2 ms2 = g_ms[d4.z];
    float2 ms3 = g_ms[d4.w];
    float sc0 = expf(t4.x - ms0.x) / ms0.y + 0.5f;
    float sc1 = expf(t4.y - ms1.x) / ms1.y + 0.5f;
    float sc2 = expf(t4.z - ms2.x) / ms2.y + 0.5f;
    float sc3 = expf(t4.w - ms3.x) / ms3.y + 0.5f;
    *(float4*)(g_score + 4 * p) = make_float4(sc0, sc1, sc2, sc3);
    unsigned long long pk0 = mkpk(sc0, 4 * p);
    unsigned long long pk1 = mkpk(sc1, 4 * p + 1);
    unsigned long long pk2 = mkpk(sc2, 4 * p + 2);
    unsigned long long pk3 = mkpk(sc3, 4 * p + 3);
    atomicMax(&g_packs[s4.x], pk0);
    atomicMax(&g_packd[d4.x], pk0);
    atomicMax(&g_packs[s4.y], pk1);
    atomicMax(&g_packd[d4.y], pk1);
    atomicMax(&g_packs[s4.z], pk2);
    atomicMax(&g_packd[d4.z], pk2);
    atomicMax(&g_packs[s4.w], pk3);
    atomicMax(&g_packd[d4.w], pk3);
}

// ---------------- merge A: apply pending removal; maxidx from packs ----------------
__global__ void k_A(const int* __restrict__ ei, int t) {
    if (iter_done(t)) return;
    int n = blockIdx.x * blockDim.x + threadIdx.x;
    if (n == 0) g_lc[(t + 1) & 1] = 0;
    if (n >= NN) return;
    if (g_rm[n]) g_nrem[n] = 0;     // commit iteration t-1 (rm==0 at t=0)
    unsigned long long p0 = g_packs[n], p1 = g_packd[n];
    g_packs[n] = 0ull; g_packd[n] = 0ull;
    float ms0 = __uint_as_float((unsigned int)(p0 >> 32));
    float ms1 = __uint_as_float((unsigned int)(p1 >> 32));
    int mi = 0;
    if (ms1 > ms0) {
        int eid = EE - (int)(unsigned int)(p1 & 0xFFFFFFFFull);
        eid = min(eid, EE - 1);
        mi = ei[eid];            // src[am1]
    } else if (ms0 > ms1) {
        int eid = EE - (int)(unsigned int)(p0 & 0xFFFFFFFFull);
        eid = min(eid, EE - 1);
        mi = ei[EE + eid];       // dst[am0]
    }
    g_maxidx[n] = mi;
}

// ---------------- merge B: mutual-match flag + partner + liveness + count -------------
__global__ void k_B(int t) {
    if (iter_done(t)) return;
    int n = blockIdx.x * blockDim.x + threadIdx.x;
    int surv = 0;
    if (n < NN) {
        int v = g_maxidx[n];
        bool nr = g_nrem[n];
        bool rm = nr && g_nrem[v] && (g_maxidx[v] == n);
        g_rm[n] = rm ? 1 : 0;
        if (rm) g_part[n] = v;
        surv = (nr && !rm) ? 1 : 0;
        g_live[n] = (unsigned char)surv;
    }
    unsigned m = __ballot_sync(0xffffffffu, surv);
    if ((threadIdx.x & 31) == 0 && m)
        atomicAdd(&g_cnt[t], __popc(m));
}

// ---------------- merge E ----------------
// t==0: packs only. t==1: raw 2-edge/thread + list build. t>=2: compacted list.
// liveness = g_live[s] && g_live[d]  (== nrem && !rm per endpoint)
__global__ void k_E(const int* __restrict__ ei, int t) {
    if (iter_done(t)) return;
    if (t == MAXIT - 1 || g_cnt[t] <= THRESH) return;

    int lane = threadIdx.x & 31;
    int outp = (t + 1) & 1;
    int stride = gridDim.x * blockDim.x;
    int start = blockIdx.x * blockDim.x + threadIdx.x;

    if (t <= 1) {
        const int totalp = EE / 2;
        int iters = (totalp + stride - 1) / stride;
        for (int it = 0; it < iters; it++) {
            int p = start + it * stride;
            bool inb = p < totalp;
            int2 s2 = make_int2(0, 0), d2 = make_int2(0, 0);
            float2 sc2 = make_float2(0.0f, 0.0f);
            if (inb) {
                s2 = *(const int2*)(ei + 2 * p);
                d2 = *(const int2*)(ei + EE + 2 * p);
                sc2 = *(const float2*)(g_score + 2 * p);
            }
            bool l0 = inb && g_live[s2.x] && g_live[d2.x];
            bool l1 = inb && g_live[s2.y] && g_live[d2.y];
            if (l0) {
                unsigned long long pk = mkpk(sc2.x, 2 * p);
                atomicMax(&g_packs[s2.x], pk);
                atomicMax(&g_packd[d2.x], pk);
            }
            if (l1) {
                unsigned long long pk = mkpk(sc2.y, 2 * p + 1);
                atomicMax(&g_packs[s2.y], pk);
                atomicMax(&g_packd[d2.y], pk);
            }
            if (t == 1) {
                unsigned m0 = __ballot_sync(0xffffffffu, l0);
                unsigned m1 = __ballot_sync(0xffffffffu, l1);
                unsigned cnt = __popc(m0) + __popc(m1);
                int base = 0;
                if (lane == 0 && cnt) base = atomicAdd(&g_lc[outp], cnt);
                base = __shfl_sync(0xffffffffu, base, 0);
                unsigned below = (1u << lane) - 1u;
                if (l0)
                    g_list[outp][base + __popc(m0 & below)] =
                        make_int4(s2.x, d2.x, 2 * p, __float_as_int(sc2.x));
                if (l1)
                    g_list[outp][base + __popc(m0) + __popc(m1 & below)] =
                        make_int4(s2.y, d2.y, 2 * p + 1, __float_as_int(sc2.y));
            }
        }
    } else {
        int total = g_lc[t & 1];
        int iters = (total + stride - 1) / stride;
        for (int it = 0; it < iters; it++) {
            int i = start + it * stride;
            bool inb = i < total;
            int4 rec;
            if (inb) rec = g_list[t & 1][i];
            bool live = inb && g_live[rec.x] && g_live[rec.y];
            if (live) {
                unsigned long long pk =
                    ((unsigned long long)(unsigned int)rec.w << 32) |
                    (unsigned int)(EE - rec.z);
                atomicMax(&g_packs[rec.x], pk);
                atomicMax(&g_packd[rec.y], pk);
            }
            unsigned mask = __ballot_sync(0xffffffffu, live);
            if (mask) {
                int leader = __ffs(mask) - 1;
                int base;
                if (lane == leader) base = atomicAdd(&g_lc[outp], __popc(mask));
                base = __shfl_sync(0xffffffffu, base, leader);
                if (live) {
                    int off = __popc(mask & ((1u << lane) - 1));
                    g_list[outp][base + off] = rec;
                }
            }
        }
    }
}

// ---------------- packed node status ----------------
__global__ void k_stat() {
    int n = blockIdx.x * blockDim.x + threadIdx.x;
    if (n >= NN) return;
    int live = (g_nrem[n] && !g_rm[n]) ? 1 : 0;
    g_stat[n] = live | ((g_part[n] + 1) << 1);
}

// ---------------- output (4 edges/thread, float4 stores) ----------------
__global__ void k_out(const int* __restrict__ ei, float* __restrict__ out) {
    int i = blockIdx.x * blockDim.x + threadIdx.x;
    int stride = gridDim.x * blockDim.x;
    for (int p = i; p < EE / 4; p += stride) {
        int4 s4 = *(const int4*)(ei + 4 * p);
        int4 d4 = *(const int4*)(ei + EE + 4 * p);
        float4 sc4 = *(const float4*)(g_score + 4 * p);
        int ss0 = g_stat[s4.x], sd0 = g_stat[d4.x];
        int ss1 = g_stat[s4.y], sd1 = g_stat[d4.y];
        int ss2 = g_stat[s4.z], sd2 = g_stat[d4.z];
        int ss3 = g_stat[s4.w], sd3 = g_stat[d4.w];
        float4 o1;
        o1.x = (ss0 & sd0 & 1) ? sc4.x : 0.0f;
        o1.y = (ss1 & sd1 & 1) ? sc4.y : 0.0f;
        o1.z = (ss2 & sd2 & 1) ? sc4.z : 0.0f;
        o1.w = (ss3 & sd3 & 1) ? sc4.w : 0.0f;
        *(float4*)(out + 4 * p) = o1;
        float4 o2;
        o2.x = (((ss0 >> 1) == d4.x + 1) && ((sd0 >> 1) == s4.x + 1)) ? 0.0f : 1.0f;
        o2.y = (((ss1 >> 1) == d4.y + 1) && ((sd1 >> 1) == s4.y + 1)) ? 0.0f : 1.0f;
        o2.z = (((ss2 >> 1) == d4.z + 1) && ((sd2 >> 1) == s4.z + 1)) ? 0.0f : 1.0f;
        o2.w = (((ss3 >> 1) == d4.w + 1) && ((sd3 >> 1) == s4.w + 1)) ? 0.0f : 1.0f;
        *(float4*)(out + EE + 4 * p) = o2;
    }
    for (int n = i; n < NN; n += stride) {
        out[2 * EE + n] = (float)(g_stat[n] & 1);
    }
}

extern "C" void kernel_launch(void* const* d_in, const int* in_sizes, int n_in,
                              void* d_out, int out_size) {
    const float* x  = (const float*)d_in[0];
    const int*   ei = (const int*)d_in[1];
    // d_in[2] = batch (unused, all zeros)
    const float* Wh = (const float*)d_in[3];
    const float* bh = (const float*)d_in[4];
    const float* Wo = (const float*)d_in[5];
    const float* bo = (const float*)d_in[6];
    float* out = (float*)d_out;

    const int e4blocks = (EE / 4 + TPB - 1) / TPB;   // 1563
    const int nblocks = (NN + TPB - 1) / TPB;        // 391
    const int pblocks = (NN + PTPB - 1) / PTPB;      // 782

    k_pre<<<pblocks, PTPB>>>(x, Wh, bh);
    k_mlp<<<MGRID, MTPB>>>(ei, Wh, bh, Wo, bo);
    k_exp<<<e4blocks, TPB>>>(ei);
    k_ms<<<nblocks, TPB>>>();
    k_soft<<<e4blocks, TPB>>>(ei);
    for (int t = 0; t < MAXIT; t++) {
        k_A<<<nblocks, TPB>>>(ei, t);
        k_B<<<nblocks, TPB>>>(t);
        k_E<<<2048, TPB>>>(ei, t);
    }
    k_stat<<<nblocks, TPB>>>();
    k_out<<<2048, TPB>>>(ei, out);
}

// round 17
// speedup vs baseline: 1.0101x; 1.0101x over previous
#include <cuda_runtime.h>

#define NN 100000
#define EE 1600000
#define CC 16
#define HH 32
#define NLAY 8
#define TPB 256
#define PTPB 128
#define MTPB 64
#define MBLK 6
#define MGRID (148 * MBLK) // 6 blocks/SM x 148 SMs, co-resident via __launch_bounds__(64,6)
#define NCHUNK 12500       // (EE/2)/64
#define MAXIT 10
#define THRESH 5000        // count <= 5000  <=>  ratio <= 0.05 (exact in fp32)

// ---------------- device scratch ----------------
__device__ unsigned int        g_mkey[NN];
__device__ double              g_ssum[NN];
__device__ float2              g_ms[NN];       // (max_logit_f32, (float)ssum) per node
__device__ float               g_tmp[EE];
__device__ float               g_score[EE];
__device__ unsigned long long  g_packs[NN];
__device__ unsigned long long  g_packd[NN];
__device__ int                 g_maxidx[NN];
__device__ int                 g_part[NN];
__device__ unsigned char       g_nrem[NN];
__device__ unsigned char       g_rm[NN];
__device__ unsigned char       g_live[NN];     // nrem && !rm (written by k_B)
__device__ int                 g_cnt[MAXIT];
__device__ int                 g_lc[2];
__device__ int4                g_list[2][EE];
__device__ float               g_P[NN * HH];   // x @ W0[:16] + b0  (src half)
__device__ float               g_Q[NN * HH];   // x @ W0[16:]       (dst half)
__device__ int                 g_stat[NN];     // livebit | (part+1)<<1 (written by k_B)

__device__ __forceinline__ unsigned int fkey(float f) {
    unsigned int b = __float_as_uint(f);
    return (b & 0x80000000u) ? ~b : (b | 0x80000000u);
}
__device__ __forceinline__ float fkey_inv(unsigned int k) {
    unsigned int b = (k & 0x80000000u) ? (k ^ 0x80000000u) : ~k;
    return __uint_as_float(b);
}
__device__ __forceinline__ bool iter_done(int t) {
    return (t > 0) && (g_cnt[t - 1] <= THRESH);
}
__device__ __forceinline__ unsigned long long mkpk(float sc, int eid) {
    return ((unsigned long long)__float_as_uint(sc) << 32) | (unsigned int)(EE - eid);
}

// ---------------- layer-1 per-node precompute + global init (fused) ----------------
__global__ void __launch_bounds__(PTPB)
k_pre(const float* __restrict__ x, const float* __restrict__ Wh,
      const float* __restrict__ bh) {
    __shared__ __align__(16) float W0[HH * HH];
    __shared__ float b0[HH];
    for (int i = threadIdx.x; i < HH * HH; i += blockDim.x) W0[i] = Wh[i];
    if (threadIdx.x < HH) b0[threadIdx.x] = bh[threadIdx.x];
    __syncthreads();

    int n = blockIdx.x * blockDim.x + threadIdx.x;

    if (n < NN) {
        g_mkey[n] = 0u;
        g_ssum[n] = 0.0;
        g_packs[n] = 0ull;       // score=0.0f, eid=E (matches empty-segment fill)
        g_packd[n] = 0ull;
        g_nrem[n] = 1;
        g_rm[n] = 0;
        g_part[n] = -1;
    }
    if (n < MAXIT) g_cnt[n] = 0;
    if (n < 2) g_lc[n] = 0;

    if (n >= NN) return;

    float xv[CC];
    const float4* xp = (const float4*)(x + (size_t)n * CC);
#pragma unroll
    for (int q = 0; q < 4; q++) {
        float4 v = xp[q];
        xv[4 * q] = v.x; xv[4 * q + 1] = v.y; xv[4 * q + 2] = v.z; xv[4 * q + 3] = v.w;
    }
    float a[HH];
#pragma unroll
    for (int j = 0; j < HH; j++) a[j] = b0[j];
#pragma unroll
    for (int k = 0; k < CC; k++) {
        float xk = xv[k];
        const float4* w4 = (const float4*)(W0 + k * HH);
#pragma unroll
        for (int j = 0; j < HH / 4; j++) {
            float4 w = w4[j];
            a[4 * j] = fmaf(xk, w.x, a[4 * j]);
            a[4 * j + 1] = fmaf(xk, w.y, a[4 * j + 1]);
            a[4 * j + 2] = fmaf(xk, w.z, a[4 * j + 2]);
            a[4 * j + 3] = fmaf(xk, w.w, a[4 * j + 3]);
        }
    }
    float4* Pp = (float4*)(g_P + (size_t)n * HH);
#pragma unroll
    for (int j = 0; j < HH / 4; j++)
        Pp[j] = make_float4(a[4 * j], a[4 * j + 1], a[4 * j + 2], a[4 * j + 3]);

#pragma unroll
    for (int j = 0; j < HH; j++) a[j] = 0.0f;
#pragma unroll
    for (int k = 0; k < CC; k++) {
        float xk = xv[k];
        const float4* w4 = (const float4*)(W0 + (CC + k) * HH);
#pragma unroll
        for (int j = 0; j < HH / 4; j++) {
            float4 w = w4[j];
            a[4 * j] = fmaf(xk, w.x, a[4 * j]);
            a[4 * j + 1] = fmaf(xk, w.y, a[4 * j + 1]);
            a[4 * j + 2] = fmaf(xk, w.z, a[4 * j + 2]);
            a[4 * j + 3] = fmaf(xk, w.w, a[4 * j + 3]);
        }
    }
    float4* Qp = (float4*)(g_Q + (size_t)n * HH);
#pragma unroll
    for (int j = 0; j < HH / 4; j++)
        Qp[j] = make_float4(a[4 * j], a[4 * j + 1], a[4 * j + 2], a[4 * j + 3]);
}

// ---------------- edge MLP layers 2..8, grid-stride persistent, 2 edges/thread -------
// Per-edge arithmetic is bit-identical to rounds 6..16 (same FMA order).
__global__ void __launch_bounds__(MTPB, MBLK)
k_mlp(const int* __restrict__ ei,
      const float* __restrict__ Wh, const float* __restrict__ bh,
      const float* __restrict__ Wo, const float* __restrict__ bo) {
    __shared__ __align__(16) float Wsh[(NLAY - 1) * HH * HH];
    __shared__ float bsh[(NLAY - 1) * HH];
    __shared__ float Wosh[HH];
    __shared__ float bosh;
    {
        const float4* src = (const float4*)(Wh + HH * HH);
        float4* dst = (float4*)Wsh;
        for (int i = threadIdx.x; i < (NLAY - 1) * HH * HH / 4; i += MTPB)
            dst[i] = src[i];
    }
    for (int i = threadIdx.x; i < (NLAY - 1) * HH; i += MTPB)
        bsh[i] = bh[HH + i];
    if (threadIdx.x < HH) Wosh[threadIdx.x] = Wo[threadIdx.x];
    if (threadIdx.x == 0) bosh = bo[0];
    __syncthreads();

    int c = blockIdx.x;
    if (c >= NCHUNK) return;
    int i0 = c * MTPB + threadIdx.x;
    int sA = ei[i0], dA = ei[EE + i0];
    int sB = ei[i0 + EE / 2], dB = ei[EE + i0 + EE / 2];

#pragma unroll 1
    for (; c < NCHUNK; c += MGRID) {
        int i = c * MTPB + threadIdx.x;   // 0 .. EE/2-1
        int eA = i;
        int eB = i + (EE / 2);

        // prefetch next chunk's indices (independent loads, scheduled early)
        int nsA = 0, ndA = 0, nsB = 0, ndB = 0;
        int cn = c + MGRID;
        if (cn < NCHUNK) {
            int in = cn * MTPB + threadIdx.x;
            nsA = ei[in];
            ndA = ei[EE + in];
            nsB = ei[in + EE / 2];
            ndB = ei[EE + in + EE / 2];
        }

        float h[2][HH];
        {
            const float4* PA = (const float4*)(g_P + (size_t)sA * HH);
            const float4* QA = (const float4*)(g_Q + (size_t)dA * HH);
            const float4* PB = (const float4*)(g_P + (size_t)sB * HH);
            const float4* QB = (const float4*)(g_Q + (size_t)dB * HH);
#pragma unroll
            for (int q = 0; q < HH / 4; q++) {
                float4 pa = PA[q], qa = QA[q];
                float4 pb = PB[q], qb = QB[q];
                h[0][4 * q + 0] = fmaxf(pa.x + qa.x, 0.0f);
                h[0][4 * q + 1] = fmaxf(pa.y + qa.y, 0.0f);
                h[0][4 * q + 2] = fmaxf(pa.z + qa.z, 0.0f);
                h[0][4 * q + 3] = fmaxf(pa.w + qa.w, 0.0f);
                h[1][4 * q + 0] = fmaxf(pb.x + qb.x, 0.0f);
                h[1][4 * q + 1] = fmaxf(pb.y + qb.y, 0.0f);
                h[1][4 * q + 2] = fmaxf(pb.z + qb.z, 0.0f);
                h[1][4 * q + 3] = fmaxf(pb.w + qb.w, 0.0f);
            }
        }

#pragma unroll 1
        for (int l = 0; l < NLAY - 1; l++) {
            float o[2][HH];
#pragma unroll
            for (int j = 0; j < HH; j++) {
                float bb = bsh[l * HH + j];
                o[0][j] = bb;
                o[1][j] = bb;
            }
            const float* Wl = Wsh + l * HH * HH;
#pragma unroll
            for (int k = 0; k < HH; k++) {
                float hA = h[0][k], hB = h[1][k];
                const float4* w4 = (const float4*)(Wl + k * HH);
#pragma unroll
                for (int j = 0; j < HH / 4; j++) {
                    float4 w = w4[j];
                    o[0][4 * j + 0] = fmaf(hA, w.x, o[0][4 * j + 0]);
                    o[0][4 * j + 1] = fmaf(hA, w.y, o[0][4 * j + 1]);
                    o[0][4 * j + 2] = fmaf(hA, w.z, o[0][4 * j + 2]);
                    o[0][4 * j + 3] = fmaf(hA, w.w, o[0][4 * j + 3]);
                    o[1][4 * j + 0] = fmaf(hB, w.x, o[1][4 * j + 0]);
                    o[1][4 * j + 1] = fmaf(hB, w.y, o[1][4 * j + 1]);
                    o[1][4 * j + 2] = fmaf(hB, w.z, o[1][4 * j + 2]);
                    o[1][4 * j + 3] = fmaf(hB, w.w, o[1][4 * j + 3]);
                }
            }
#pragma unroll
            for (int j = 0; j < HH; j++) {
                h[0][j] = fmaxf(o[0][j], 0.0f);
                h[1][j] = fmaxf(o[1][j], 0.0f);
            }
        }

        float accA = bosh, accB = bosh;
#pragma unroll
        for (int k = 0; k < HH; k++) {
            float w = Wosh[k];
            accA = fmaf(h[0][k], w, accA);
            accB = fmaf(h[1][k], w, accB);
        }

        g_tmp[eA] = accA;
        atomicMax(&g_mkey[dA], fkey(accA));
        g_tmp[eB] = accB;
        atomicMax(&g_mkey[dB], fkey(accB));

        sA = nsA; dA = ndA; sB = nsB; dB = ndB;
    }
}

// ---------------- exp + segment sum (2 edges/thread) ----------------
__global__ void k_exp(const int* __restrict__ ei) {
    int p = blockIdx.x * blockDim.x + threadIdx.x;
    if (p >= EE / 2) return;
    int2 d2 = *(const int2*)(ei + EE + 2 * p);
    float2 t2 = *(const float2*)(g_tmp + 2 * p);
    float m0 = fkey_inv(g_mkey[d2.x]);
    float m1 = fkey_inv(g_mkey[d2.y]);
    atomicAdd(&g_ssum[d2.x], (double)expf(t2.x - m0));
    atomicAdd(&g_ssum[d2.y], (double)expf(t2.y - m1));
}

// ---------------- per-node (max, sum_f32) pack (4 nodes/thread, vectorized) ----------
__global__ void k_ms() {
    int q = blockIdx.x * blockDim.x + threadIdx.x;
    int n0 = 4 * q;
    if (n0 >= NN) return;
    if (n0 + 3 < NN) {
        uint4 mk = *(const uint4*)(g_mkey + n0);
        double2 sa = *(const double2*)(g_ssum + n0);
        double2 sb = *(const double2*)(g_ssum + n0 + 2);
        g_ms[n0] = make_float2(fkey_inv(mk.x), (float)sa.x);
        g_ms[n0 + 1] = make_float2(fkey_inv(mk.y), (float)sa.y);
        g_ms[n0 + 2] = make_float2(fkey_inv(mk.z), (float)sb.x);
        g_ms[n0 + 3] = make_float2(fkey_inv(mk.w), (float)sb.y);
    } else {
        for (int n = n0; n < NN; n++)
            g_ms[n] = make_float2(fkey_inv(g_mkey[n]), (float)g_ssum[n]);
    }
}

// ---------------- softmax finalize (2 edges/thread, one random 8B load/edge) --------
__global__ void k_soft(const int* __restrict__ ei) {
    int p = blockIdx.x * blockDim.x + threadIdx.x;
    if (p >= EE / 2) return;
    int2 s2 = *(const int2*)(ei + 2 * p);
    int2 d2 = *(const int2*)(ei + EE + 2 * p);
    float2 t2 = *(const float2*)(g_tmp + 2 * p);
    float2 ms0 = g_ms[d2.x];
    float2 ms1 = g_ms[d2.y];
    float sc0 = expf(t2.x - ms0.x) / ms0.y + 0.5f;   // same bits as exp/(float)ssum
    float sc1 = expf(t2.y - ms1.x) / ms1.y + 0.5f;
    *(float2*)(g_score + 2 * p) = make_float2(sc0, sc1);
    unsigned long long pk0 = mkpk(sc0, 2 * p);
    unsigned long long pk1 = mkpk(sc1, 2 * p + 1);
    atomicMax(&g_packs[s2.x], pk0);
    atomicMax(&g_packd[d2.x], pk0);
    atomicMax(&g_packs[s2.y], pk1);
    atomicMax(&g_packd[d2.y], pk1);
}

// ---------------- merge A: apply pending removal; maxidx from packs ----------------
__global__ void k_A(const int* __restrict__ ei, int t) {
    if (iter_done(t)) return;
    int n = blockIdx.x * blockDim.x + threadIdx.x;
    if (n == 0) g_lc[(t + 1) & 1] = 0;
    if (n >= NN) return;
    if (g_rm[n]) g_nrem[n] = 0;     // commit iteration t-1 (rm==0 at t=0)
    unsigned long long p0 = g_packs[n], p1 = g_packd[n];
    g_packs[n] = 0ull; g_packd[n] = 0ull;
    float ms0 = __uint_as_float((unsigned int)(p0 >> 32));
    float ms1 = __uint_as_float((unsigned int)(p1 >> 32));
    int mi = 0;
    if (ms1 > ms0) {
        int eid = EE - (int)(unsigned int)(p1 & 0xFFFFFFFFull);
        eid = min(eid, EE - 1);
        mi = ei[eid];            // src[am1]
    } else if (ms0 > ms1) {
        int eid = EE - (int)(unsigned int)(p0 & 0xFFFFFFFFull);
        eid = min(eid, EE - 1);
        mi = ei[EE + eid];       // dst[am0]
    }
    g_maxidx[n] = mi;
}

// ---------------- merge B: mutual match + partner + liveness + stat + count ----------
// The last executed iteration's write of g_stat is exactly the final node status
// (frozen iterations skip this kernel, preserving it).
__global__ void k_B(int t) {
    if (iter_done(t)) return;
    int n = blockIdx.x * blockDim.x + threadIdx.x;
    int surv = 0;
    if (n < NN) {
        int v = g_maxidx[n];
        bool nr = g_nrem[n];
        bool rm = nr && g_nrem[v] && (g_maxidx[v] == n);
        g_rm[n] = rm ? 1 : 0;
        int part = rm ? v : g_part[n];
        if (rm) g_part[n] = v;
        surv = (nr && !rm) ? 1 : 0;
        g_live[n] = (unsigned char)surv;
        g_stat[n] = surv | ((part + 1) << 1);
    }
    unsigned m = __ballot_sync(0xffffffffu, surv);
    if ((threadIdx.x & 31) == 0 && m)
        atomicAdd(&g_cnt[t], __popc(m));
}

// ---------------- merge E ----------------
// t==0: packs only. t==1: raw 2-edge/thread + list build. t>=2: compacted list.
// liveness = g_live[s] && g_live[d]  (== nrem && !rm per endpoint)
__global__ void k_E(const int* __restrict__ ei, int t) {
    if (iter_done(t)) return;
    if (t == MAXIT - 1 || g_cnt[t] <= THRESH) return;

    int lane = threadIdx.x & 31;
    int outp = (t + 1) & 1;
    int stride = gridDim.x * blockDim.x;
    int start = blockIdx.x * blockDim.x + threadIdx.x;

    if (t <= 1) {
        const int totalp = EE / 2;
        int iters = (totalp + stride - 1) / stride;
        for (int it = 0; it < iters; it++) {
            int p = start + it * stride;
            bool inb = p < totalp;
            int2 s2 = make_int2(0, 0), d2 = make_int2(0, 0);
            float2 sc2 = make_float2(0.0f, 0.0f);
            if (inb) {
                s2 = *(const int2*)(ei + 2 * p);
                d2 = *(const int2*)(ei + EE + 2 * p);
                sc2 = *(const float2*)(g_score + 2 * p);
            }
            bool l0 = inb && g_live[s2.x] && g_live[d2.x];
            bool l1 = inb && g_live[s2.y] && g_live[d2.y];
            if (l0) {
                unsigned long long pk = mkpk(sc2.x, 2 * p);
                atomicMax(&g_packs[s2.x], pk);
                atomicMax(&g_packd[d2.x], pk);
            }
            if (l1) {
                unsigned long long pk = mkpk(sc2.y, 2 * p + 1);
                atomicMax(&g_packs[s2.y], pk);
                atomicMax(&g_packd[d2.y], pk);
            }
            if (t == 1) {
                unsigned m0 = __ballot_sync(0xffffffffu, l0);
                unsigned m1 = __ballot_sync(0xffffffffu, l1);
                unsigned cnt = __popc(m0) + __popc(m1);
                int base = 0;
                if (lane == 0 && cnt) base = atomicAdd(&g_lc[outp], cnt);
                base = __shfl_sync(0xffffffffu, base, 0);
                unsigned below = (1u << lane) - 1u;
                if (l0)
                    g_list[outp][base + __popc(m0 & below)] =
                        make_int4(s2.x, d2.x, 2 * p, __float_as_int(sc2.x));
                if (l1)
                    g_list[outp][base + __popc(m0) + __popc(m1 & below)] =
                        make_int4(s2.y, d2.y, 2 * p + 1, __float_as_int(sc2.y));
            }
        }
    } else {
        int total = g_lc[t & 1];
        int iters = (total + stride - 1) / stride;
        for (int it = 0; it < iters; it++) {
            int i = start + it * stride;
            bool inb = i < total;
            int4 rec;
            if (inb) rec = g_list[t & 1][i];
            bool live = inb && g_live[rec.x] && g_live[rec.y];
            if (live) {
                unsigned long long pk =
                    ((unsigned long long)(unsigned int)rec.w << 32) |
                    (unsigned int)(EE - rec.z);
                atomicMax(&g_packs[rec.x], pk);
                atomicMax(&g_packd[rec.y], pk);
            }
            unsigned mask = __ballot_sync(0xffffffffu, live);
            if (mask) {
                int leader = __ffs(mask) - 1;
                int base;
                if (lane == leader) base = atomicAdd(&g_lc[outp], __popc(mask));
                base = __shfl_sync(0xffffffffu, base, leader);
                if (live) {
                    int off = __popc(mask & ((1u << lane) - 1));
                    g_list[outp][base + off] = rec;
                }
            }
        }
    }
}

// ---------------- output (2 edges/thread, float2 stores) ----------------
__global__ void k_out(const int* __restrict__ ei, float* __restrict__ out) {
    int i = blockIdx.x * blockDim.x + threadIdx.x;
    int stride = gridDim.x * blockDim.x;
    for (int p = i; p < EE / 2; p += stride) {
        int2 s2 = *(const int2*)(ei + 2 * p);
        int2 d2 = *(const int2*)(ei + EE + 2 * p);
        float2 sc2 = *(const float2*)(g_score + 2 * p);
        int ss0 = g_stat[s2.x], sd0 = g_stat[d2.x];
        int ss1 = g_stat[s2.y], sd1 = g_stat[d2.y];
        float2 o1;
        o1.x = (ss0 & sd0 & 1) ? sc2.x : 0.0f;
        o1.y = (ss1 & sd1 & 1) ? sc2.y : 0.0f;
        *(float2*)(out + 2 * p) = o1;
        float2 o2;
        o2.x = (((ss0 >> 1) == d2.x + 1) && ((sd0 >> 1) == s2.x + 1)) ? 0.0f : 1.0f;
        o2.y = (((ss1 >> 1) == d2.y + 1) && ((sd1 >> 1) == s2.y + 1)) ? 0.0f : 1.0f;
        *(float2*)(out + EE + 2 * p) = o2;
    }
    for (int n = i; n < NN; n += stride) {
        out[2 * EE + n] = (float)(g_stat[n] & 1);
    }
}

extern "C" void kernel_launch(void* const* d_in, const int* in_sizes, int n_in,
                              void* d_out, int out_size) {
    const float* x  = (const float*)d_in[0];
    const int*   ei = (const int*)d_in[1];
    // d_in[2] = batch (unused, all zeros)
    const float* Wh = (const float*)d_in[3];
    const float* bh = (const float*)d_in[4];
    const float* Wo = (const float*)d_in[5];
    const float* bo = (const float*)d_in[6];
    float* out = (float*)d_out;

    const int e2blocks = (EE / 2 + TPB - 1) / TPB;      // 3125
    const int nblocks = (NN + TPB - 1) / TPB;           // 391
    const int n4blocks = (NN / 4 + TPB - 1) / TPB;      // 98
    const int pblocks = (NN + PTPB - 1) / PTPB;         // 782

    k_pre<<<pblocks, PTPB>>>(x, Wh, bh);
    k_mlp<<<MGRID, MTPB>>>(ei, Wh, bh, Wo, bo);
    k_exp<<<e2blocks, TPB>>>(ei);
    k_ms<<<n4blocks, TPB>>>();
    k_soft<<<e2blocks, TPB>>>(ei);
    for (int t = 0; t < MAXIT; t++) {
        k_A<<<nblocks, TPB>>>(ei, t);
        k_B<<<nblocks, TPB>>>(t);
        k_E<<<2048, TPB>>>(ei, t);
    }
    k_out<<<2048, TPB>>>(ei, out);
}